// round 1
// baseline (speedup 1.0000x reference)
#include <cuda_runtime.h>
#include <float.h>

#define NIMG 32
#define H    512
#define W    512
#define HW   (H * W)
#define CHW  (3 * HW)

// Scratch (allocations are forbidden; __device__ globals are the sanctioned path)
__device__ float g_hmax[NIMG * HW];      // horizontal-max intermediate, 33.5 MB
__device__ float g_partial[512];         // per-block partial sums

// ---------------------------------------------------------------------------
// Kernel 1: channel max of (1 - img) + horizontal 35-wide sliding max.
// One block per (n, h) row. 128 threads.
// Decomposition: width-35 = 7 taps (stride 5) over a width-5 sliding max.
// ---------------------------------------------------------------------------
__global__ __launch_bounds__(128) void hpass_kernel(const float* __restrict__ img) {
    const int row = blockIdx.x;            // 0 .. NIMG*H-1
    const int n   = row >> 9;
    const int h   = row & (H - 1);
    const float* p = img + (size_t)n * CHW + (size_t)h * W;

    __shared__ float s[W + 64];            // c values, padded 32 each side
    __shared__ float t[W + 64];            // width-5 left-aligned sliding max

    const int tid = threadIdx.x;

    // pads = -FLT_MAX (window always contains >=18 valid pixels, pad never wins)
    if (tid < 64) {
        int i = (tid < 32) ? tid : (W + 32) + (tid - 32);
        s[i] = -FLT_MAX;
    }

    // middle: 128 threads x float4 = 512 px. c = 1 - min(ch0, ch1, ch2)
    const float4 a = ((const float4*)p)[tid];
    const float4 b = ((const float4*)(p + HW))[tid];
    const float4 c = ((const float4*)(p + 2 * HW))[tid];
    float4 r;
    r.x = 1.0f - fminf(a.x, fminf(b.x, c.x));
    r.y = 1.0f - fminf(a.y, fminf(b.y, c.y));
    r.z = 1.0f - fminf(a.z, fminf(b.z, c.z));
    r.w = 1.0f - fminf(a.w, fminf(b.w, c.w));
    ((float4*)(s + 32))[tid] = r;
    __syncthreads();

    // width-5 pass: t[j] = max(s[j..j+4]), j in [0, 571]
    #pragma unroll
    for (int i = tid; i < W + 60; i += 128) {
        float m = s[i];
        m = fmaxf(m, s[i + 1]);
        m = fmaxf(m, s[i + 2]);
        m = fmaxf(m, s[i + 3]);
        m = fmaxf(m, s[i + 4]);
        t[i] = m;
    }
    __syncthreads();

    // combine: dc[w] = max over 7 taps of t, covering s[w+15 .. w+49] (35 px)
    float* out = g_hmax + (size_t)row * W;
    #pragma unroll
    for (int w = tid; w < W; w += 128) {
        const int j = w + 15;
        float m = t[j];
        m = fmaxf(m, t[j + 5]);
        m = fmaxf(m, t[j + 10]);
        m = fmaxf(m, t[j + 15]);
        m = fmaxf(m, t[j + 20]);
        m = fmaxf(m, t[j + 25]);
        m = fmaxf(m, t[j + 30]);
        out[w] = m;
    }
}

// ---------------------------------------------------------------------------
// Kernel 2: vertical 35-tall sliding max + |.| sum reduction.
// One block per (n, 32-column tile) = 512 blocks. 512 threads.
// Dynamic smem: s[(H+64)*32] + t[(H+64)*32] = 147456 B.
// Layout [row][col], col = tid%32 -> conflict-free, coalesced global access.
// ---------------------------------------------------------------------------
__global__ __launch_bounds__(512) void vpass_kernel() {
    const int n  = blockIdx.x >> 4;
    const int wb = (blockIdx.x & 15) << 5;

    extern __shared__ float sm[];
    float* s = sm;                         // (H+64)*32
    float* t = sm + (H + 64) * 32;         // (H+64)*32 (uses first (H+60)*32)

    const int tid = threadIdx.x;
    const float* src = g_hmax + (size_t)n * HW + wb;

    // load (padded rows = -FLT_MAX)
    #pragma unroll 4
    for (int idx = tid; idx < (H + 64) * 32; idx += 512) {
        const int r = (idx >> 5) - 32;
        const int w = idx & 31;
        s[idx] = (r >= 0 && r < H) ? src[(size_t)r * W + w] : -FLT_MAX;
    }
    __syncthreads();

    // vertical width-5 pass
    #pragma unroll 4
    for (int idx = tid; idx < (H + 60) * 32; idx += 512) {
        float m = s[idx];
        m = fmaxf(m, s[idx + 32]);
        m = fmaxf(m, s[idx + 64]);
        m = fmaxf(m, s[idx + 96]);
        m = fmaxf(m, s[idx + 128]);
        t[idx] = m;
    }
    __syncthreads();

    // 7-tap combine + accumulate |dc|
    float acc = 0.0f;
    #pragma unroll 4
    for (int idx = tid; idx < H * 32; idx += 512) {
        const int base = idx + 15 * 32;
        float m = t[base];
        m = fmaxf(m, t[base +  5 * 32]);
        m = fmaxf(m, t[base + 10 * 32]);
        m = fmaxf(m, t[base + 15 * 32]);
        m = fmaxf(m, t[base + 20 * 32]);
        m = fmaxf(m, t[base + 25 * 32]);
        m = fmaxf(m, t[base + 30 * 32]);
        acc += fabsf(m);
    }

    // block reduction (512 -> 1), deterministic per block
    __shared__ float red[16];
    #pragma unroll
    for (int off = 16; off; off >>= 1)
        acc += __shfl_down_sync(0xffffffffu, acc, off);
    if ((tid & 31) == 0) red[tid >> 5] = acc;
    __syncthreads();
    if (tid < 16) {
        float v = red[tid];
        #pragma unroll
        for (int off = 8; off; off >>= 1)
            v += __shfl_down_sync(0xffffu, v, off);
        if (tid == 0) g_partial[blockIdx.x] = v;
    }
}

// ---------------------------------------------------------------------------
// Kernel 3: final reduction of 512 partials -> mean
// ---------------------------------------------------------------------------
__global__ __launch_bounds__(512) void finish_kernel(float* __restrict__ out) {
    const int tid = threadIdx.x;
    float v = g_partial[tid];
    __shared__ float red[16];
    #pragma unroll
    for (int off = 16; off; off >>= 1)
        v += __shfl_down_sync(0xffffffffu, v, off);
    if ((tid & 31) == 0) red[tid >> 5] = v;
    __syncthreads();
    if (tid < 16) {
        float x = red[tid];
        #pragma unroll
        for (int off = 8; off; off >>= 1)
            x += __shfl_down_sync(0xffffu, x, off);
        if (tid == 0) out[0] = x * (1.0f / ((float)NIMG * (float)HW));
    }
}

// ---------------------------------------------------------------------------
extern "C" void kernel_launch(void* const* d_in, const int* in_sizes, int n_in,
                              void* d_out, int out_size) {
    const float* img = (const float*)d_in[0];
    float* out = (float*)d_out;

    const int vsmem = (H + 64) * 32 * 2 * (int)sizeof(float);  // 147456 B
    cudaFuncSetAttribute(vpass_kernel,
                         cudaFuncAttributeMaxDynamicSharedMemorySize, vsmem);

    hpass_kernel<<<NIMG * H, 128>>>(img);
    vpass_kernel<<<512, 512, vsmem>>>();
    finish_kernel<<<1, 512>>>(out);
}

// round 2
// speedup vs baseline: 1.2768x; 1.2768x over previous
#include <cuda_runtime.h>
#include <cuda_fp16.h>
#include <float.h>

#define NIMG 32
#define H    512
#define W    512
#define HW   (H * W)
#define CHW  (3 * HW)

#define RT   128              // vpass rows per tile
#define NRT  (H / RT)         // 4 row tiles
#define NCT  (W / 32)         // 16 col tiles
#define VBLOCKS (NIMG * NRT * NCT)   // 2048

// Scratch (__device__ globals; allocations forbidden)
__device__ __half g_hmax[NIMG * HW];      // 16.75 MB fp16 intermediate
__device__ float  g_partial[VBLOCKS];

// ---------------------------------------------------------------------------
// Kernel 1: c = 1 - min3(channels), then horizontal 35-wide sliding max.
// One block per (n, h) row, 128 threads. width-35 = 7 taps over width-5 pass.
// Output stored as fp16 (values in [0,1], rel-err <= 4.9e-4 << 1e-3 gate).
// ---------------------------------------------------------------------------
__global__ __launch_bounds__(128) void hpass_kernel(const float* __restrict__ img) {
    const int row = blockIdx.x;
    const int n   = row >> 9;
    const int h   = row & (H - 1);
    const float* p = img + (size_t)n * CHW + (size_t)h * W;

    __shared__ float s[W + 64];
    __shared__ float t[W + 64];

    const int tid = threadIdx.x;

    if (tid < 64) {
        int i = (tid < 32) ? tid : (W + 32) + (tid - 32);
        s[i] = -FLT_MAX;
    }

    const float4 a = ((const float4*)p)[tid];
    const float4 b = ((const float4*)(p + HW))[tid];
    const float4 c = ((const float4*)(p + 2 * HW))[tid];
    float4 r;
    r.x = 1.0f - fminf(a.x, fminf(b.x, c.x));
    r.y = 1.0f - fminf(a.y, fminf(b.y, c.y));
    r.z = 1.0f - fminf(a.z, fminf(b.z, c.z));
    r.w = 1.0f - fminf(a.w, fminf(b.w, c.w));
    ((float4*)(s + 32))[tid] = r;
    __syncthreads();

    #pragma unroll
    for (int i = tid; i < W + 60; i += 128) {
        float m = s[i];
        m = fmaxf(m, s[i + 1]);
        m = fmaxf(m, s[i + 2]);
        m = fmaxf(m, s[i + 3]);
        m = fmaxf(m, s[i + 4]);
        t[i] = m;
    }
    __syncthreads();

    __half* out = g_hmax + (size_t)row * W;
    #pragma unroll
    for (int w = tid; w < W; w += 128) {
        const int j = w + 15;
        float m = t[j];
        m = fmaxf(m, t[j + 5]);
        m = fmaxf(m, t[j + 10]);
        m = fmaxf(m, t[j + 15]);
        m = fmaxf(m, t[j + 20]);
        m = fmaxf(m, t[j + 25]);
        m = fmaxf(m, t[j + 30]);
        out[w] = __float2half_rn(m);
    }
}

// ---------------------------------------------------------------------------
// Kernel 2: vertical 35-tall sliding max over a 128-row x 32-col tile + |.| sum.
// 2048 blocks x 256 threads. smem ~40 KB -> 4-5 blocks/SM.
//   s rows: global rows [r0-17, r0+144]  (162 rows)
//   t[j]   = max(s[j..j+4])              (158 rows)
//   out i  = max over taps t[i + 5k], k=0..6  (covers s[i..i+34])
// ---------------------------------------------------------------------------
__global__ __launch_bounds__(256) void vpass_kernel() {
    const int bx = blockIdx.x;
    const int n  = bx >> 6;                 // 64 tiles per image
    const int ct = (bx >> 2) & 15;
    const int rt = bx & 3;
    const int wb = ct << 5;
    const int r0 = rt * RT;

    __shared__ float s[(RT + 34) * 32];     // 162*32
    __shared__ float t[(RT + 30) * 32];     // 158*32

    const int tid = threadIdx.x;
    const __half* src = g_hmax + (size_t)n * HW + wb;

    #pragma unroll 4
    for (int idx = tid; idx < (RT + 34) * 32; idx += 256) {
        const int r = r0 - 17 + (idx >> 5);
        const int w = idx & 31;
        s[idx] = (r >= 0 && r < H) ? __half2float(src[(size_t)r * W + w]) : -FLT_MAX;
    }
    __syncthreads();

    #pragma unroll 4
    for (int idx = tid; idx < (RT + 30) * 32; idx += 256) {
        float m = s[idx];
        m = fmaxf(m, s[idx + 32]);
        m = fmaxf(m, s[idx + 64]);
        m = fmaxf(m, s[idx + 96]);
        m = fmaxf(m, s[idx + 128]);
        t[idx] = m;
    }
    __syncthreads();

    float acc = 0.0f;
    #pragma unroll 4
    for (int idx = tid; idx < RT * 32; idx += 256) {
        float m = t[idx];
        m = fmaxf(m, t[idx + 160]);
        m = fmaxf(m, t[idx + 320]);
        m = fmaxf(m, t[idx + 480]);
        m = fmaxf(m, t[idx + 640]);
        m = fmaxf(m, t[idx + 800]);
        m = fmaxf(m, t[idx + 960]);
        acc += fabsf(m);
    }

    __shared__ float red[8];
    #pragma unroll
    for (int off = 16; off; off >>= 1)
        acc += __shfl_down_sync(0xffffffffu, acc, off);
    if ((tid & 31) == 0) red[tid >> 5] = acc;
    __syncthreads();
    if (tid < 8) {
        float v = red[tid];
        #pragma unroll
        for (int off = 4; off; off >>= 1)
            v += __shfl_down_sync(0xffu, v, off);
        if (tid == 0) g_partial[bx] = v;
    }
}

// ---------------------------------------------------------------------------
// Kernel 3: reduce 2048 partials -> mean
// ---------------------------------------------------------------------------
__global__ __launch_bounds__(1024) void finish_kernel(float* __restrict__ out) {
    const int tid = threadIdx.x;
    float v = g_partial[tid] + g_partial[tid + 1024];
    __shared__ float red[32];
    #pragma unroll
    for (int off = 16; off; off >>= 1)
        v += __shfl_down_sync(0xffffffffu, v, off);
    if ((tid & 31) == 0) red[tid >> 5] = v;
    __syncthreads();
    if (tid < 32) {
        float x = red[tid];
        #pragma unroll
        for (int off = 16; off; off >>= 1)
            x += __shfl_down_sync(0xffffffffu, x, off);
        if (tid == 0) out[0] = x * (1.0f / ((float)NIMG * (float)HW));
    }
}

// ---------------------------------------------------------------------------
extern "C" void kernel_launch(void* const* d_in, const int* in_sizes, int n_in,
                              void* d_out, int out_size) {
    const float* img = (const float*)d_in[0];
    float* out = (float*)d_out;

    hpass_kernel<<<NIMG * H, 128>>>(img);
    vpass_kernel<<<VBLOCKS, 256>>>();
    finish_kernel<<<1, 1024>>>(out);
}

// round 3
// speedup vs baseline: 1.7897x; 1.4016x over previous
#include <cuda_runtime.h>
#include <cuda_fp16.h>
#include <float.h>

#define NIMG 32
#define H    512
#define W    512
#define HW   (H * W)
#define CHW  (3 * HW)

#define NEG2 0xFC00FC00u      // half2(-inf, -inf)

#define VR   128              // vpass output rows per tile
#define VBLOCKS (NIMG * 4 * 8)   // 32 imgs x 4 row tiles x 8 col tiles = 1024

__device__ __half g_hmax[NIMG * HW];     // fp16 intermediate (16.75 MB)
__device__ float  g_partial[VBLOCKS];

// packed half2 max on uint-carried values
__device__ __forceinline__ unsigned hmax2u(unsigned a, unsigned b) {
    __half2 ha = *reinterpret_cast<__half2*>(&a);
    __half2 hb = *reinterpret_cast<__half2*>(&b);
    __half2 hm = __hmax2(ha, hb);
    return *reinterpret_cast<unsigned*>(&hm);
}
// (A.hi, B.lo) — shift-by-one-pixel across half2 boundary
__device__ __forceinline__ unsigned sh1(unsigned a, unsigned b) {
    return __byte_perm(a, b, 0x5432);
}

// ---------------------------------------------------------------------------
// Kernel 1: c = 1 - min3(channels) -> fp16, horizontal 35-wide sliding max.
// One block per (n,h) row, 128 threads. All smem traffic is packed half2.
// s2[i] holds pixels (2i-20, 2i-19); t[j] = max(s[j..j+4]) in t2 pairs;
// out[w] = max_{k=0..6} t[w-17+5k].
// ---------------------------------------------------------------------------
__global__ __launch_bounds__(128) void hpass_kernel(const float* __restrict__ img) {
    const int row = blockIdx.x;
    const int n   = row >> 9;
    const int h   = row & (H - 1);
    const float* p = img + (size_t)n * CHW + (size_t)h * W;

    __shared__ unsigned s2[276];   // px -20 .. 531
    __shared__ unsigned t2[276];   // t px -20 .. 524 (idx 0..272)

    const int tid = threadIdx.x;

    if (tid < 20) s2[tid < 10 ? tid : 256 + tid] = NEG2;   // pads

    const float4 a = ((const float4*)p)[tid];
    const float4 b = ((const float4*)(p + HW))[tid];
    const float4 c = ((const float4*)(p + 2 * HW))[tid];
    float c0 = 1.0f - fminf(a.x, fminf(b.x, c.x));
    float c1 = 1.0f - fminf(a.y, fminf(b.y, c.y));
    float c2 = 1.0f - fminf(a.z, fminf(b.z, c.z));
    float c3 = 1.0f - fminf(a.w, fminf(b.w, c.w));
    __half2 h01 = __floats2half2_rn(c0, c1);
    __half2 h23 = __floats2half2_rn(c2, c3);
    s2[2 * tid + 10] = *reinterpret_cast<unsigned*>(&h01);
    s2[2 * tid + 11] = *reinterpret_cast<unsigned*>(&h23);
    __syncthreads();

    // width-5 pass: t2[i] = (max s[2i-20..2i-16], max s[2i-19..2i-15])
    #pragma unroll
    for (int i = tid; i < 273; i += 128) {
        const unsigned A = s2[i], B = s2[i + 1], C = s2[i + 2];
        const unsigned m01 = hmax2u(A, sh1(A, B));
        const unsigned m23 = hmax2u(B, sh1(B, C));
        t2[i] = hmax2u(hmax2u(m01, m23), C);
    }
    __syncthreads();

    // combine: outputs (w, w+1), w = 2q. taps at px w-17+5k, k=0..6.
    unsigned* orow = (unsigned*)(g_hmax + (size_t)row * W);
    #pragma unroll
    for (int q = tid; q < 256; q += 128) {
        unsigned v;
        v = sh1(t2[q + 1], t2[q + 2]);              // k=0 (odd start)
        v = hmax2u(v, t2[q + 4]);                    // k=1 (aligned)
        v = hmax2u(v, sh1(t2[q + 6], t2[q + 7]));    // k=2
        v = hmax2u(v, t2[q + 9]);                    // k=3
        v = hmax2u(v, sh1(t2[q + 11], t2[q + 12]));  // k=4
        v = hmax2u(v, t2[q + 14]);                   // k=5
        v = hmax2u(v, sh1(t2[q + 16], t2[q + 17]));  // k=6
        orow[q] = v;
    }
}

// ---------------------------------------------------------------------------
// Kernel 2: vertical 35-tall sliding max over 128-row x 64-col tile + sum.
// 1024 blocks x 256 threads. smem 41 KB static, all packed half2.
// s rows: global [r0-17, r0+144] (162). t[r] = max(s[r..r+4]) (158 rows).
// out k: max over t[k+5j], j=0..6. Sum |dc| in fp32.
// ---------------------------------------------------------------------------
__global__ __launch_bounds__(256) void vpass_kernel() {
    const int bx = blockIdx.x;
    const int n  = bx >> 5;
    const int rt = (bx >> 3) & 3;
    const int ct = bx & 7;
    const int r0 = rt * VR;
    const int wb = ct * 64;           // column offset in halves

    __shared__ unsigned sv[162 * 32];   // [row][32 half2-cols]
    __shared__ unsigned tv[158 * 32];

    const int tid = threadIdx.x;
    const __half* srcbase = g_hmax + (size_t)n * HW + wb;

    // load: uint4 = 8 halves; 8 uint4 per 64-col row
    #pragma unroll 2
    for (int idx = tid; idx < 162 * 8; idx += 256) {
        const int rr = idx >> 3, q = idx & 7;
        const int gr = r0 - 17 + rr;
        uint4 v;
        if (gr >= 0 && gr < H)
            v = ((const uint4*)(srcbase + (size_t)gr * W))[q];
        else
            v = make_uint4(NEG2, NEG2, NEG2, NEG2);
        ((uint4*)sv)[idx] = v;
    }
    __syncthreads();

    // vertical width-5 pass (row stride = 8 uint4)
    #pragma unroll 2
    for (int idx = tid; idx < 158 * 8; idx += 256) {
        const uint4* sp = (const uint4*)sv;
        uint4 x0 = sp[idx], x1 = sp[idx + 8], x2 = sp[idx + 16],
              x3 = sp[idx + 24], x4 = sp[idx + 32];
        uint4 m;
        m.x = hmax2u(hmax2u(hmax2u(x0.x, x1.x), hmax2u(x2.x, x3.x)), x4.x);
        m.y = hmax2u(hmax2u(hmax2u(x0.y, x1.y), hmax2u(x2.y, x3.y)), x4.y);
        m.z = hmax2u(hmax2u(hmax2u(x0.z, x1.z), hmax2u(x2.z, x3.z)), x4.z);
        m.w = hmax2u(hmax2u(hmax2u(x0.w, x1.w), hmax2u(x2.w, x3.w)), x4.w);
        ((uint4*)tv)[idx] = m;
    }
    __syncthreads();

    // 7-tap combine (stride 5 rows = 40 uint4) + accumulate
    float acc = 0.0f;
    #pragma unroll 2
    for (int idx = tid; idx < 128 * 8; idx += 256) {
        const uint4* tp = (const uint4*)tv;
        uint4 m = tp[idx];
        #pragma unroll
        for (int j = 1; j < 7; j++) {
            uint4 t = tp[idx + 40 * j];
            m.x = hmax2u(m.x, t.x);
            m.y = hmax2u(m.y, t.y);
            m.z = hmax2u(m.z, t.z);
            m.w = hmax2u(m.w, t.w);
        }
        float2 f0 = __half22float2(*reinterpret_cast<__half2*>(&m.x));
        float2 f1 = __half22float2(*reinterpret_cast<__half2*>(&m.y));
        float2 f2 = __half22float2(*reinterpret_cast<__half2*>(&m.z));
        float2 f3 = __half22float2(*reinterpret_cast<__half2*>(&m.w));
        acc += (f0.x + f0.y) + (f1.x + f1.y) + (f2.x + f2.y) + (f3.x + f3.y);
    }

    __shared__ float red[8];
    #pragma unroll
    for (int off = 16; off; off >>= 1)
        acc += __shfl_down_sync(0xffffffffu, acc, off);
    if ((tid & 31) == 0) red[tid >> 5] = acc;
    __syncthreads();
    if (tid < 8) {
        float v = red[tid];
        #pragma unroll
        for (int off = 4; off; off >>= 1)
            v += __shfl_down_sync(0xffu, v, off);
        if (tid == 0) g_partial[bx] = v;
    }
}

// ---------------------------------------------------------------------------
// Kernel 3: reduce 1024 partials -> mean
// ---------------------------------------------------------------------------
__global__ __launch_bounds__(1024) void finish_kernel(float* __restrict__ out) {
    const int tid = threadIdx.x;
    float v = g_partial[tid];
    __shared__ float red[32];
    #pragma unroll
    for (int off = 16; off; off >>= 1)
        v += __shfl_down_sync(0xffffffffu, v, off);
    if ((tid & 31) == 0) red[tid >> 5] = v;
    __syncthreads();
    if (tid < 32) {
        float x = red[tid];
        #pragma unroll
        for (int off = 16; off; off >>= 1)
            x += __shfl_down_sync(0xffffffffu, x, off);
        if (tid == 0) out[0] = x * (1.0f / ((float)NIMG * (float)HW));
    }
}

// ---------------------------------------------------------------------------
extern "C" void kernel_launch(void* const* d_in, const int* in_sizes, int n_in,
                              void* d_out, int out_size) {
    const float* img = (const float*)d_in[0];
    float* out = (float*)d_out;

    hpass_kernel<<<NIMG * H, 128>>>(img);
    vpass_kernel<<<VBLOCKS, 256>>>();
    finish_kernel<<<1, 1024>>>(out);
}